// round 2
// baseline (speedup 1.0000x reference)
#include <cuda_runtime.h>
#include <cuda_bf16.h>
#include <math.h>

// Problem constants
#define B_  8
#define L_  2050
#define D_  320
#define M1  (B_ * L_)   // 16400 rows for x @ W

// 21 MB scratch for xW (allocation-free requirement -> __device__ global)
__device__ float g_xW[(size_t)M1 * D_];

#define TM 128
#define TN 128
#define TK 16

// ---------------------------------------------------------------------------
// Kernel 1: NN GEMM  g_xW = x @ W   (M=16400, N=320, K=320)
// ---------------------------------------------------------------------------
__global__ __launch_bounds__(256, 2)
void xw_gemm_nn(const float* __restrict__ X, const float* __restrict__ W)
{
    __shared__ __align__(16) float As[TK][TM];
    __shared__ __align__(16) float Bs[TK][TN];

    const int tid = threadIdx.x;
    const int m0 = blockIdx.y * TM;
    const int n0 = blockIdx.x * TN;

    // A-tile load mapping: 128 rows x 16 k  -> 2 float4 per thread
    const int ar  = tid >> 2;          // 0..63
    const int ak  = (tid & 3) << 2;    // 0,4,8,12
    // B-tile (W) load mapping: 16 k x 128 n -> 2 float4 per thread
    const int bkr = tid >> 5;          // 0..7
    const int bnc = (tid & 31) << 2;   // 0..124

    const int tx = tid & 15;
    const int ty = tid >> 4;

    float acc[8][8];
#pragma unroll
    for (int i = 0; i < 8; ++i)
#pragma unroll
        for (int j = 0; j < 8; ++j) acc[i][j] = 0.f;

    for (int k0 = 0; k0 < D_; k0 += TK) {
        // load A (x) tile, k-major transpose
#pragma unroll
        for (int t = 0; t < 2; ++t) {
            int row = ar + t * 64;
            int gm = m0 + row;
            float4 v = make_float4(0.f, 0.f, 0.f, 0.f);
            if (gm < M1)
                v = *(const float4*)&X[(size_t)gm * D_ + k0 + ak];
            As[ak + 0][row] = v.x; As[ak + 1][row] = v.y;
            As[ak + 2][row] = v.z; As[ak + 3][row] = v.w;
        }
        // load B (W) tile
#pragma unroll
        for (int t = 0; t < 2; ++t) {
            int kk = bkr + t * 8;
            int gn = n0 + bnc;
            float4 v = make_float4(0.f, 0.f, 0.f, 0.f);
            if (gn < D_)
                v = *(const float4*)&W[(size_t)(k0 + kk) * D_ + gn];
            Bs[kk][bnc + 0] = v.x; Bs[kk][bnc + 1] = v.y;
            Bs[kk][bnc + 2] = v.z; Bs[kk][bnc + 3] = v.w;
        }
        __syncthreads();

#pragma unroll
        for (int k = 0; k < TK; ++k) {
            float4 a0 = *(const float4*)&As[k][ty * 8];
            float4 a1 = *(const float4*)&As[k][ty * 8 + 4];
            float4 b0 = *(const float4*)&Bs[k][tx * 8];
            float4 b1 = *(const float4*)&Bs[k][tx * 8 + 4];
            float a[8] = {a0.x, a0.y, a0.z, a0.w, a1.x, a1.y, a1.z, a1.w};
            float b[8] = {b0.x, b0.y, b0.z, b0.w, b1.x, b1.y, b1.z, b1.w};
#pragma unroll
            for (int i = 0; i < 8; ++i)
#pragma unroll
                for (int j = 0; j < 8; ++j)
                    acc[i][j] = fmaf(a[i], b[j], acc[i][j]);
        }
        __syncthreads();
    }

#pragma unroll
    for (int i = 0; i < 8; ++i) {
        int gm = m0 + ty * 8 + i;
        if (gm >= M1) continue;
#pragma unroll
        for (int j = 0; j < 8; ++j) {
            int gn = n0 + tx * 8 + j;
            if (gn < D_)
                g_xW[(size_t)gm * D_ + gn] = acc[i][j];
        }
    }
}

// ---------------------------------------------------------------------------
// Kernel 2: batched NT GEMM + sigmoid epilogue
//   out[b,i,j] = sigmoid( xW[b,i,:] . x[b,j,:] + bias )
// ---------------------------------------------------------------------------
__global__ __launch_bounds__(256, 2)
void logits_gemm_nt_sigmoid(const float* __restrict__ X,
                            const float* __restrict__ bias,
                            float* __restrict__ Out)
{
    __shared__ __align__(16) float As[TK][TM];
    __shared__ __align__(16) float Bs[TK][TN];

    const int bz = blockIdx.z;
    const float* Ab = g_xW + (size_t)bz * L_ * D_;
    const float* Bb = X    + (size_t)bz * L_ * D_;
    float*       Cb = Out  + (size_t)bz * L_ * L_;

    const int tid = threadIdx.x;
    const int m0 = blockIdx.y * TM;
    const int n0 = blockIdx.x * TN;

    const int ar = tid >> 2;          // 0..63
    const int ak = (tid & 3) << 2;    // 0,4,8,12

    const int tx = tid & 15;
    const int ty = tid >> 4;

    float acc[8][8];
#pragma unroll
    for (int i = 0; i < 8; ++i)
#pragma unroll
        for (int j = 0; j < 8; ++j) acc[i][j] = 0.f;

    for (int k0 = 0; k0 < D_; k0 += TK) {
#pragma unroll
        for (int t = 0; t < 2; ++t) {
            int row = ar + t * 64;
            int gm = m0 + row;
            float4 av = make_float4(0.f, 0.f, 0.f, 0.f);
            if (gm < L_)
                av = *(const float4*)&Ab[(size_t)gm * D_ + k0 + ak];
            As[ak + 0][row] = av.x; As[ak + 1][row] = av.y;
            As[ak + 2][row] = av.z; As[ak + 3][row] = av.w;

            int gn = n0 + row;
            float4 bv = make_float4(0.f, 0.f, 0.f, 0.f);
            if (gn < L_)
                bv = *(const float4*)&Bb[(size_t)gn * D_ + k0 + ak];
            Bs[ak + 0][row] = bv.x; Bs[ak + 1][row] = bv.y;
            Bs[ak + 2][row] = bv.z; Bs[ak + 3][row] = bv.w;
        }
        __syncthreads();

#pragma unroll
        for (int k = 0; k < TK; ++k) {
            float4 a0 = *(const float4*)&As[k][ty * 8];
            float4 a1 = *(const float4*)&As[k][ty * 8 + 4];
            float4 b0 = *(const float4*)&Bs[k][tx * 8];
            float4 b1 = *(const float4*)&Bs[k][tx * 8 + 4];
            float a[8] = {a0.x, a0.y, a0.z, a0.w, a1.x, a1.y, a1.z, a1.w};
            float b[8] = {b0.x, b0.y, b0.z, b0.w, b1.x, b1.y, b1.z, b1.w};
#pragma unroll
            for (int i = 0; i < 8; ++i)
#pragma unroll
                for (int j = 0; j < 8; ++j)
                    acc[i][j] = fmaf(a[i], b[j], acc[i][j]);
        }
        __syncthreads();
    }

    const float bv = bias[0];
#pragma unroll
    for (int i = 0; i < 8; ++i) {
        int gm = m0 + ty * 8 + i;
        if (gm >= L_) continue;
#pragma unroll
        for (int j = 0; j < 8; ++j) {
            int gn = n0 + tx * 8 + j;
            if (gn < L_) {
                float v = acc[i][j] + bv;
                Cb[(size_t)gm * L_ + gn] = 1.0f / (1.0f + expf(-v));
            }
        }
    }
}

// ---------------------------------------------------------------------------
extern "C" void kernel_launch(void* const* d_in, const int* in_sizes, int n_in,
                              void* d_out, int out_size)
{
    const float* x  = (const float*)d_in[0];   // (B, L, D) fp32
    const float* W  = (const float*)d_in[1];   // (D, D) fp32
    const float* bb = (const float*)d_in[2];   // (1,)  fp32
    float* out = (float*)d_out;                // (B, L, L) fp32

    // Kernel 1: xW = x @ W
    {
        dim3 grid((D_ + TN - 1) / TN, (M1 + TM - 1) / TM, 1);  // (3, 129)
        xw_gemm_nn<<<grid, 256>>>(x, W);
    }
    // Kernel 2: out = sigmoid(xW @ x^T + b), batched over B
    {
        dim3 grid((L_ + TN - 1) / TN, (L_ + TM - 1) / TM, B_); // (17, 17, 8)
        logits_gemm_nt_sigmoid<<<grid, 256>>>(x, bb, out);
    }
}

// round 4
// speedup vs baseline: 2.1011x; 2.1011x over previous
#include <cuda_runtime.h>
#include <cuda_bf16.h>
#include <math.h>
#include <stdint.h>

// Problem constants
#define B_  8
#define L_  2050
#define D_  320
#define M1  (B_ * L_)   // 16400

// ---------------------------------------------------------------------------
// Device-global scratch (allocation-free rule)
// ---------------------------------------------------------------------------
__device__ __nv_bfloat16 g_xh[(size_t)M1 * D_];
__device__ __nv_bfloat16 g_xl[(size_t)M1 * D_];
__device__ __nv_bfloat16 g_wth[D_ * D_];   // W transposed: [e][k]
__device__ __nv_bfloat16 g_wtl[D_ * D_];
__device__ __nv_bfloat16 g_xwh[(size_t)M1 * D_];
__device__ __nv_bfloat16 g_xwl[(size_t)M1 * D_];

// ---------------------------------------------------------------------------
// Split helpers
// ---------------------------------------------------------------------------
__device__ __forceinline__ void split_bf16(float v, __nv_bfloat16& h, __nv_bfloat16& l) {
    h = __float2bfloat16(v);
    l = __float2bfloat16(v - __bfloat162float(h));
}

__global__ void split_x_kernel(const float* __restrict__ x) {
    int i = blockIdx.x * blockDim.x + threadIdx.x;
    const int n4 = M1 * D_ / 4;
    if (i >= n4) return;
    float4 v = ((const float4*)x)[i];
    __nv_bfloat16 h[4], l[4];
    float vs[4] = {v.x, v.y, v.z, v.w};
#pragma unroll
    for (int j = 0; j < 4; ++j) split_bf16(vs[j], h[j], l[j]);
    __nv_bfloat162* ph = (__nv_bfloat162*)g_xh;
    __nv_bfloat162* pl = (__nv_bfloat162*)g_xl;
    ph[2 * i + 0] = __nv_bfloat162{h[0], h[1]};
    ph[2 * i + 1] = __nv_bfloat162{h[2], h[3]};
    pl[2 * i + 0] = __nv_bfloat162{l[0], l[1]};
    pl[2 * i + 1] = __nv_bfloat162{l[2], l[3]};
}

__global__ void split_w_kernel(const float* __restrict__ W) {
    int i = blockIdx.x * blockDim.x + threadIdx.x;
    if (i >= D_ * D_) return;
    int k = i / D_, e = i % D_;
    __nv_bfloat16 h, l;
    split_bf16(W[i], h, l);
    g_wth[e * D_ + k] = h;
    g_wtl[e * D_ + k] = l;
}

// ---------------------------------------------------------------------------
// MMA / ldmatrix / cp.async primitives
// ---------------------------------------------------------------------------
__device__ __forceinline__ void cpasync16(uint32_t dst, const void* src, bool valid) {
    int sz = valid ? 16 : 0;
    asm volatile("cp.async.cg.shared.global [%0], [%1], 16, %2;\n"
                 :: "r"(dst), "l"(src), "r"(sz));
}
__device__ __forceinline__ void cp_commit() { asm volatile("cp.async.commit_group;\n"); }
template <int N>
__device__ __forceinline__ void cp_wait() { asm volatile("cp.async.wait_group %0;\n" :: "n"(N)); }

__device__ __forceinline__ void ldsm4(uint32_t& r0, uint32_t& r1, uint32_t& r2, uint32_t& r3, uint32_t addr) {
    asm volatile("ldmatrix.sync.aligned.m8n8.x4.shared.b16 {%0,%1,%2,%3}, [%4];\n"
                 : "=r"(r0), "=r"(r1), "=r"(r2), "=r"(r3) : "r"(addr));
}
__device__ __forceinline__ void mma16816(float* c, const uint32_t* a, const uint32_t* b) {
    asm volatile("mma.sync.aligned.m16n8k16.row.col.f32.bf16.bf16.f32 "
                 "{%0,%1,%2,%3}, {%4,%5,%6,%7}, {%8,%9}, {%0,%1,%2,%3};\n"
                 : "+f"(c[0]), "+f"(c[1]), "+f"(c[2]), "+f"(c[3])
                 : "r"(a[0]), "r"(a[1]), "r"(a[2]), "r"(a[3]), "r"(b[0]), "r"(b[1]));
}

// ---------------------------------------------------------------------------
// GEMM tile geometry
// ---------------------------------------------------------------------------
#define BM 128
#define BN 128
#define BK 32
#define SSTR 40                                  // bf16 per smem row (pad: conflict-free ldmatrix)
#define ARR_BYTES (128 * SSTR * 2)               // 10240
#define STAGE_BYTES (4 * ARR_BYTES)              // 40960
#define OFF_AH 0
#define OFF_AL (1 * ARR_BYTES)
#define OFF_BH (2 * ARR_BYTES)
#define OFF_BL (3 * ARR_BYTES)
#define SMEM_TOTAL (2 * STAGE_BYTES)             // 81920

// SIG=false: GEMM1  xW = x @ W      (A=g_xh/l [M1,D], B=g_wth/l [D,D]) -> split to g_xwh/l
// SIG=true : GEMM2  out = sigmoid(xW @ x^T + b), batched over blockIdx.z
template <bool SIG>
__global__ __launch_bounds__(256, 1)
void gemm_bf16x3(const float* __restrict__ bias, float* __restrict__ Out)
{
    extern __shared__ char smem[];
    const uint32_t sbase = (uint32_t)__cvta_generic_to_shared(smem);

    const int M = SIG ? L_ : M1;
    const int N = SIG ? L_ : D_;

    const __nv_bfloat16* Ah = SIG ? g_xwh : g_xh;
    const __nv_bfloat16* Al = SIG ? g_xwl : g_xl;
    const __nv_bfloat16* Bh = SIG ? g_xh  : g_wth;
    const __nv_bfloat16* Bl = SIG ? g_xl  : g_wtl;
    if (SIG) {
        size_t off = (size_t)blockIdx.z * L_ * D_;
        Ah += off; Al += off; Bh += off; Bl += off;
    }

    const int m0 = blockIdx.y * BM;
    const int n0 = blockIdx.x * BN;
    const int tid = threadIdx.x;
    const int lane = tid & 31;
    const int wid = tid >> 5;
    const int wm = (wid >> 2) * 64;   // 0 / 64
    const int wn = (wid & 3) * 32;    // 0..96
    const int gid = lane >> 2, tig = lane & 3;

    float acc[4][4][4];
#pragma unroll
    for (int i = 0; i < 4; ++i)
#pragma unroll
        for (int j = 0; j < 4; ++j)
#pragma unroll
            for (int f = 0; f < 4; ++f) acc[i][j][f] = 0.f;

    // ldmatrix per-thread address components (within tile)
    const int a_m = wm + ((lane >> 3) & 1) * 8 + (lane & 7);   // + mi*16
    const int a_k = ((lane >> 4) & 1) * 8;                     // + ks*16
    const int b_n = wn + ((lane >> 4) & 1) * 8 + (lane & 7);   // + p*16
    const int b_k = ((lane >> 3) & 1) * 8;                     // + ks*16

    // Stage loader: 4 arrays x 128 rows x 32 bf16 (4 x 16B segs per row)
    auto load_stage = [&](int kt, int s) {
        const int k0 = kt * BK;
        const uint32_t sb = sbase + s * STAGE_BYTES;
#pragma unroll
        for (int h = 0; h < 2; ++h) {
            int c = tid + h * 256;            // 0..511
            int row = c >> 2, seg = c & 3;
            bool av = (m0 + row) < M;
            bool bv = (n0 + row) < N;
            size_t aoff = (size_t)(av ? m0 + row : 0) * D_ + k0 + seg * 8;
            size_t boff = (size_t)(bv ? n0 + row : 0) * D_ + k0 + seg * 8;
            uint32_t sm = row * (SSTR * 2) + seg * 16;
            cpasync16(sb + OFF_AH + sm, Ah + aoff, av);
            cpasync16(sb + OFF_AL + sm, Al + aoff, av);
            cpasync16(sb + OFF_BH + sm, Bh + boff, bv);
            cpasync16(sb + OFF_BL + sm, Bl + boff, bv);
        }
        cp_commit();
    };

    const int KT = D_ / BK;   // 10
    load_stage(0, 0);

    for (int kt = 0; kt < KT; ++kt) {
        if (kt + 1 < KT) { load_stage(kt + 1, (kt + 1) & 1); cp_wait<1>(); }
        else             { cp_wait<0>(); }
        __syncthreads();

        const uint32_t sb = sbase + (kt & 1) * STAGE_BYTES;
#pragma unroll
        for (int ks = 0; ks < 2; ++ks) {
            uint32_t ah[4][4], al[4][4], bh[2][4], bl[2][4];
#pragma unroll
            for (int mi = 0; mi < 4; ++mi) {
                uint32_t adr = sb + (a_m + mi * 16) * (SSTR * 2) + (ks * 16 + a_k) * 2;
                ldsm4(ah[mi][0], ah[mi][1], ah[mi][2], ah[mi][3], adr + OFF_AH);
                ldsm4(al[mi][0], al[mi][1], al[mi][2], al[mi][3], adr + OFF_AL);
            }
#pragma unroll
            for (int p = 0; p < 2; ++p) {
                uint32_t adr = sb + (b_n + p * 16) * (SSTR * 2) + (ks * 16 + b_k) * 2;
                ldsm4(bh[p][0], bh[p][1], bh[p][2], bh[p][3], adr + OFF_BH);
                ldsm4(bl[p][0], bl[p][1], bl[p][2], bl[p][3], adr + OFF_BL);
            }
#pragma unroll
            for (int mi = 0; mi < 4; ++mi)
#pragma unroll
                for (int ni = 0; ni < 4; ++ni) {
                    float* c = acc[mi][ni];
                    const uint32_t* pbh = &bh[ni >> 1][(ni & 1) * 2];
                    const uint32_t* pbl = &bl[ni >> 1][(ni & 1) * 2];
                    mma16816(c, ah[mi], pbh);
                    mma16816(c, ah[mi], pbl);
                    mma16816(c, al[mi], pbh);
                }
        }
        __syncthreads();
    }

    // -------------------- epilogue --------------------
    if (SIG) {
        const float bv = bias[0];
        float* Cb = Out + (size_t)blockIdx.z * L_ * L_;
#pragma unroll
        for (int mi = 0; mi < 4; ++mi)
#pragma unroll
            for (int half = 0; half < 2; ++half) {
                int gm = m0 + wm + mi * 16 + gid + half * 8;
                if (gm >= M) continue;
#pragma unroll
                for (int ni = 0; ni < 4; ++ni) {
                    int gn = n0 + wn + ni * 8 + 2 * tig;
                    if (gn >= N) continue;
                    float v0 = acc[mi][ni][half * 2 + 0] + bv;
                    float v1 = acc[mi][ni][half * 2 + 1] + bv;
                    float2 r;
                    r.x = 1.0f / (1.0f + expf(-v0));
                    r.y = 1.0f / (1.0f + expf(-v1));
                    *(float2*)&Cb[(size_t)gm * L_ + gn] = r;
                }
            }
    } else {
#pragma unroll
        for (int mi = 0; mi < 4; ++mi)
#pragma unroll
            for (int half = 0; half < 2; ++half) {
                int gm = m0 + wm + mi * 16 + gid + half * 8;
                if (gm >= M) continue;
#pragma unroll
                for (int ni = 0; ni < 4; ++ni) {
                    int gn = n0 + wn + ni * 8 + 2 * tig;
                    if (gn >= N) continue;
                    float v0 = acc[mi][ni][half * 2 + 0];
                    float v1 = acc[mi][ni][half * 2 + 1];
                    __nv_bfloat16 h0, l0, h1, l1;
                    split_bf16(v0, h0, l0);
                    split_bf16(v1, h1, l1);
                    size_t idx = (size_t)gm * D_ + gn;
                    *(__nv_bfloat162*)&g_xwh[idx] = __nv_bfloat162{h0, h1};
                    *(__nv_bfloat162*)&g_xwl[idx] = __nv_bfloat162{l0, l1};
                }
            }
    }
}

// ---------------------------------------------------------------------------
extern "C" void kernel_launch(void* const* d_in, const int* in_sizes, int n_in,
                              void* d_out, int out_size)
{
    const float* x  = (const float*)d_in[0];   // (B, L, D)
    const float* W  = (const float*)d_in[1];   // (D, D)
    const float* bb = (const float*)d_in[2];   // (1,)
    float* out = (float*)d_out;                // (B, L, L)

    // Opt-in smem (no stream interaction; legal during graph capture).
    (void)cudaFuncSetAttribute(gemm_bf16x3<false>, cudaFuncAttributeMaxDynamicSharedMemorySize, SMEM_TOTAL);
    (void)cudaFuncSetAttribute(gemm_bf16x3<true>,  cudaFuncAttributeMaxDynamicSharedMemorySize, SMEM_TOTAL);

    // 1) split inputs into bf16 hi/lo
    {
        int n4 = M1 * D_ / 4;
        split_x_kernel<<<(n4 + 255) / 256, 256>>>(x);
        split_w_kernel<<<(D_ * D_ + 255) / 256, 256>>>(W);
    }
    // 2) xW = x @ W  (writes split bf16 scratch)
    {
        dim3 grid((D_ + BN - 1) / BN, (M1 + BM - 1) / BM, 1);   // (3, 129)
        gemm_bf16x3<false><<<grid, 256, SMEM_TOTAL>>>(nullptr, nullptr);
    }
    // 3) out = sigmoid(xW @ x^T + b), batched
    {
        dim3 grid((L_ + BN - 1) / BN, (L_ + BM - 1) / BM, B_);  // (17, 17, 8)
        gemm_bf16x3<true><<<grid, 256, SMEM_TOTAL>>>(bb, out);
    }
}

// round 7
// speedup vs baseline: 2.7293x; 1.2989x over previous
#include <cuda_runtime.h>
#include <cuda_bf16.h>
#include <math.h>
#include <stdint.h>

// Problem constants
#define B_  8
#define L_  2050
#define D_  320
#define M1  (B_ * L_)   // 16400

// ---------------------------------------------------------------------------
// Device-global scratch (allocation-free rule)
// ---------------------------------------------------------------------------
__device__ __nv_bfloat16 g_xh[(size_t)M1 * D_];
__device__ __nv_bfloat16 g_xl[(size_t)M1 * D_];
__device__ __nv_bfloat16 g_wth[D_ * D_];   // W transposed: [e][k]
__device__ __nv_bfloat16 g_wtl[D_ * D_];
__device__ __nv_bfloat16 g_xwh[(size_t)M1 * D_];
__device__ __nv_bfloat16 g_xwl[(size_t)M1 * D_];

// ---------------------------------------------------------------------------
// Split helpers
// ---------------------------------------------------------------------------
__device__ __forceinline__ void split_bf16(float v, __nv_bfloat16& h, __nv_bfloat16& l) {
    h = __float2bfloat16(v);
    l = __float2bfloat16(v - __bfloat162float(h));
}

__global__ void split_x_kernel(const float* __restrict__ x) {
    int i = blockIdx.x * blockDim.x + threadIdx.x;
    const int n4 = M1 * D_ / 4;
    if (i >= n4) return;
    float4 v = ((const float4*)x)[i];
    __nv_bfloat16 h[4], l[4];
    float vs[4] = {v.x, v.y, v.z, v.w};
#pragma unroll
    for (int j = 0; j < 4; ++j) split_bf16(vs[j], h[j], l[j]);
    __nv_bfloat162* ph = (__nv_bfloat162*)g_xh;
    __nv_bfloat162* pl = (__nv_bfloat162*)g_xl;
    ph[2 * i + 0] = __nv_bfloat162{h[0], h[1]};
    ph[2 * i + 1] = __nv_bfloat162{h[2], h[3]};
    pl[2 * i + 0] = __nv_bfloat162{l[0], l[1]};
    pl[2 * i + 1] = __nv_bfloat162{l[2], l[3]};
}

__global__ void split_w_kernel(const float* __restrict__ W) {
    int i = blockIdx.x * blockDim.x + threadIdx.x;
    if (i >= D_ * D_) return;
    int k = i / D_, e = i % D_;
    __nv_bfloat16 h, l;
    split_bf16(W[i], h, l);
    g_wth[e * D_ + k] = h;
    g_wtl[e * D_ + k] = l;
}

// ---------------------------------------------------------------------------
// MMA / ldmatrix / cp.async primitives
// ---------------------------------------------------------------------------
__device__ __forceinline__ void cpasync16(uint32_t dst, const void* src, bool valid) {
    int sz = valid ? 16 : 0;
    asm volatile("cp.async.cg.shared.global [%0], [%1], 16, %2;\n"
                 :: "r"(dst), "l"(src), "r"(sz));
}
__device__ __forceinline__ void cp_commit() { asm volatile("cp.async.commit_group;\n"); }
template <int N>
__device__ __forceinline__ void cp_wait() { asm volatile("cp.async.wait_group %0;\n" :: "n"(N)); }

__device__ __forceinline__ void ldsm4(uint32_t& r0, uint32_t& r1, uint32_t& r2, uint32_t& r3, uint32_t addr) {
    asm volatile("ldmatrix.sync.aligned.m8n8.x4.shared.b16 {%0,%1,%2,%3}, [%4];\n"
                 : "=r"(r0), "=r"(r1), "=r"(r2), "=r"(r3) : "r"(addr));
}
__device__ __forceinline__ void mma16816(float* c, const uint32_t* a, const uint32_t* b) {
    asm volatile("mma.sync.aligned.m16n8k16.row.col.f32.bf16.bf16.f32 "
                 "{%0,%1,%2,%3}, {%4,%5,%6,%7}, {%8,%9}, {%0,%1,%2,%3};\n"
                 : "+f"(c[0]), "+f"(c[1]), "+f"(c[2]), "+f"(c[3])
                 : "r"(a[0]), "r"(a[1]), "r"(a[2]), "r"(a[3]), "r"(b[0]), "r"(b[1]));
}

__device__ __forceinline__ float fast_sigmoid(float v) {
    return 1.0f / (1.0f + __expf(-v));
}

// ---------------------------------------------------------------------------
// GEMM tile geometry
// ---------------------------------------------------------------------------
#define BM 128
#define BN 128
#define BK 32
#define SSTR 40                                  // bf16 per smem row (pad: conflict-free ldmatrix)
#define ARR_BYTES (128 * SSTR * 2)               // 10240
#define STAGE_BYTES (4 * ARR_BYTES)              // 40960
#define OFF_AH 0
#define OFF_AL (1 * ARR_BYTES)
#define OFF_BH (2 * ARR_BYTES)
#define OFF_BL (3 * ARR_BYTES)
#define SMEM_TOTAL (2 * STAGE_BYTES)             // 81920

// SIG=false: GEMM1  xW = x @ W      (A=g_xh/l [M1,D], B=g_wth/l [D,D]) -> split to g_xwh/l
// SIG=true : GEMM2  out = sigmoid(xW @ x^T + b), batched over blockIdx.z
// __launch_bounds__(256, 2): cap regs at 128 so TWO CTAs co-reside per SM
// (round-4 profile: regs=145 -> 1 CTA/SM -> occ 12.4%, tensor pipe starved at 41%).
template <bool SIG>
__global__ __launch_bounds__(256, 2)
void gemm_bf16x3(const float* __restrict__ bias, float* __restrict__ Out)
{
    extern __shared__ char smem[];
    const uint32_t sbase = (uint32_t)__cvta_generic_to_shared(smem);

    const int M = SIG ? L_ : M1;
    const int N = SIG ? L_ : D_;

    const __nv_bfloat16* Ah = SIG ? g_xwh : g_xh;
    const __nv_bfloat16* Al = SIG ? g_xwl : g_xl;
    const __nv_bfloat16* Bh = SIG ? g_xh  : g_wth;
    const __nv_bfloat16* Bl = SIG ? g_xl  : g_wtl;
    if (SIG) {
        size_t off = (size_t)blockIdx.z * L_ * D_;
        Ah += off; Al += off; Bh += off; Bl += off;
    }

    const int m0 = blockIdx.y * BM;
    const int n0 = blockIdx.x * BN;
    const int tid = threadIdx.x;
    const int lane = tid & 31;
    const int wid = tid >> 5;
    const int wm = (wid >> 2) * 64;   // 0 / 64
    const int wn = (wid & 3) * 32;    // 0..96
    const int gid = lane >> 2, tig = lane & 3;

    float acc[4][4][4];
#pragma unroll
    for (int i = 0; i < 4; ++i)
#pragma unroll
        for (int j = 0; j < 4; ++j)
#pragma unroll
            for (int f = 0; f < 4; ++f) acc[i][j][f] = 0.f;

    // ldmatrix per-thread address components (within tile)
    const int a_m = wm + ((lane >> 3) & 1) * 8 + (lane & 7);   // + mi*16
    const int a_k = ((lane >> 4) & 1) * 8;                     // + ks*16
    const int b_n = wn + ((lane >> 4) & 1) * 8 + (lane & 7);   // + p*16
    const int b_k = ((lane >> 3) & 1) * 8;                     // + ks*16

    // Stage loader: 4 arrays x 128 rows x 32 bf16 (4 x 16B segs per row)
    auto load_stage = [&](int kt, int s) {
        const int k0 = kt * BK;
        const uint32_t sb = sbase + s * STAGE_BYTES;
#pragma unroll
        for (int h = 0; h < 2; ++h) {
            int c = tid + h * 256;            // 0..511
            int row = c >> 2, seg = c & 3;
            bool av = (m0 + row) < M;
            bool bv = (n0 + row) < N;
            size_t aoff = (size_t)(av ? m0 + row : 0) * D_ + k0 + seg * 8;
            size_t boff = (size_t)(bv ? n0 + row : 0) * D_ + k0 + seg * 8;
            uint32_t sm = row * (SSTR * 2) + seg * 16;
            cpasync16(sb + OFF_AH + sm, Ah + aoff, av);
            cpasync16(sb + OFF_AL + sm, Al + aoff, av);
            cpasync16(sb + OFF_BH + sm, Bh + boff, bv);
            cpasync16(sb + OFF_BL + sm, Bl + boff, bv);
        }
        cp_commit();
    };

    const int KT = D_ / BK;   // 10
    load_stage(0, 0);

    for (int kt = 0; kt < KT; ++kt) {
        if (kt + 1 < KT) { load_stage(kt + 1, (kt + 1) & 1); cp_wait<1>(); }
        else             { cp_wait<0>(); }
        __syncthreads();

        const uint32_t sb = sbase + (kt & 1) * STAGE_BYTES;
#pragma unroll
        for (int ks = 0; ks < 2; ++ks) {
            uint32_t ah[4][4], al[4][4], bh[2][4], bl[2][4];
#pragma unroll
            for (int mi = 0; mi < 4; ++mi) {
                uint32_t adr = sb + (a_m + mi * 16) * (SSTR * 2) + (ks * 16 + a_k) * 2;
                ldsm4(ah[mi][0], ah[mi][1], ah[mi][2], ah[mi][3], adr + OFF_AH);
                ldsm4(al[mi][0], al[mi][1], al[mi][2], al[mi][3], adr + OFF_AL);
            }
#pragma unroll
            for (int p = 0; p < 2; ++p) {
                uint32_t adr = sb + (b_n + p * 16) * (SSTR * 2) + (ks * 16 + b_k) * 2;
                ldsm4(bh[p][0], bh[p][1], bh[p][2], bh[p][3], adr + OFF_BH);
                ldsm4(bl[p][0], bl[p][1], bl[p][2], bl[p][3], adr + OFF_BL);
            }
#pragma unroll
            for (int mi = 0; mi < 4; ++mi)
#pragma unroll
                for (int ni = 0; ni < 4; ++ni) {
                    float* c = acc[mi][ni];
                    const uint32_t* pbh = &bh[ni >> 1][(ni & 1) * 2];
                    const uint32_t* pbl = &bl[ni >> 1][(ni & 1) * 2];
                    mma16816(c, ah[mi], pbh);
                    mma16816(c, ah[mi], pbl);
                    mma16816(c, al[mi], pbh);
                }
        }
        __syncthreads();
    }

    // -------------------- epilogue --------------------
    if (SIG) {
        const float bv = bias[0];
        float* Cb = Out + (size_t)blockIdx.z * L_ * L_;
#pragma unroll
        for (int mi = 0; mi < 4; ++mi)
#pragma unroll
            for (int half = 0; half < 2; ++half) {
                int gm = m0 + wm + mi * 16 + gid + half * 8;
                if (gm >= M) continue;
#pragma unroll
                for (int ni = 0; ni < 4; ++ni) {
                    int gn = n0 + wn + ni * 8 + 2 * tig;
                    if (gn >= N) continue;
                    float2 r;
                    r.x = fast_sigmoid(acc[mi][ni][half * 2 + 0] + bv);
                    r.y = fast_sigmoid(acc[mi][ni][half * 2 + 1] + bv);
                    *(float2*)&Cb[(size_t)gm * L_ + gn] = r;
                }
            }
    } else {
#pragma unroll
        for (int mi = 0; mi < 4; ++mi)
#pragma unroll
            for (int half = 0; half < 2; ++half) {
                int gm = m0 + wm + mi * 16 + gid + half * 8;
                if (gm >= M) continue;
#pragma unroll
                for (int ni = 0; ni < 4; ++ni) {
                    int gn = n0 + wn + ni * 8 + 2 * tig;
                    if (gn >= N) continue;
                    float v0 = acc[mi][ni][half * 2 + 0];
                    float v1 = acc[mi][ni][half * 2 + 1];
                    __nv_bfloat16 h0, l0, h1, l1;
                    split_bf16(v0, h0, l0);
                    split_bf16(v1, h1, l1);
                    size_t idx = (size_t)gm * D_ + gn;
                    *(__nv_bfloat162*)&g_xwh[idx] = __nv_bfloat162{h0, h1};
                    *(__nv_bfloat162*)&g_xwl[idx] = __nv_bfloat162{l0, l1};
                }
            }
    }
}

// ---------------------------------------------------------------------------
extern "C" void kernel_launch(void* const* d_in, const int* in_sizes, int n_in,
                              void* d_out, int out_size)
{
    const float* x  = (const float*)d_in[0];   // (B, L, D)
    const float* W  = (const float*)d_in[1];   // (D, D)
    const float* bb = (const float*)d_in[2];   // (1,)
    float* out = (float*)d_out;                // (B, L, L)

    (void)cudaFuncSetAttribute(gemm_bf16x3<false>, cudaFuncAttributeMaxDynamicSharedMemorySize, SMEM_TOTAL);
    (void)cudaFuncSetAttribute(gemm_bf16x3<true>,  cudaFuncAttributeMaxDynamicSharedMemorySize, SMEM_TOTAL);

    // 1) split inputs into bf16 hi/lo
    {
        int n4 = M1 * D_ / 4;
        split_x_kernel<<<(n4 + 255) / 256, 256>>>(x);
        split_w_kernel<<<(D_ * D_ + 255) / 256, 256>>>(W);
    }
    // 2) xW = x @ W  (writes split bf16 scratch)
    {
        dim3 grid((D_ + BN - 1) / BN, (M1 + BM - 1) / BM, 1);   // (3, 129)
        gemm_bf16x3<false><<<grid, 256, SMEM_TOTAL>>>(nullptr, nullptr);
    }
    // 3) out = sigmoid(xW @ x^T + b), batched
    {
        dim3 grid((L_ + BN - 1) / BN, (L_ + BM - 1) / BM, B_);  // (17, 17, 8)
        gemm_bf16x3<true><<<grid, 256, SMEM_TOTAL>>>(bb, out);
    }
}

// round 9
// speedup vs baseline: 3.3577x; 1.2303x over previous
#include <cuda_runtime.h>
#include <cuda_bf16.h>
#include <math.h>
#include <stdint.h>

// Problem constants
#define B_  8
#define L_  2050
#define D_  320
#define M1  (B_ * L_)   // 16400

// ---------------------------------------------------------------------------
// Device-global scratch (allocation-free rule)
// ---------------------------------------------------------------------------
__device__ __nv_bfloat16 g_xh[(size_t)M1 * D_];
__device__ __nv_bfloat16 g_xl[(size_t)M1 * D_];
__device__ __nv_bfloat16 g_wth[D_ * D_];   // W transposed: [e][k]
__device__ __nv_bfloat16 g_wtl[D_ * D_];
__device__ __nv_bfloat16 g_xwh[(size_t)M1 * D_];
__device__ __nv_bfloat16 g_xwl[(size_t)M1 * D_];

// ---------------------------------------------------------------------------
// Split helpers
// ---------------------------------------------------------------------------
__device__ __forceinline__ void split_bf16(float v, __nv_bfloat16& h, __nv_bfloat16& l) {
    h = __float2bfloat16(v);
    l = __float2bfloat16(v - __bfloat162float(h));
}

__global__ void split_x_kernel(const float* __restrict__ x) {
    int i = blockIdx.x * blockDim.x + threadIdx.x;
    const int n4 = M1 * D_ / 4;
    if (i >= n4) return;
    float4 v = ((const float4*)x)[i];
    __nv_bfloat16 h[4], l[4];
    float vs[4] = {v.x, v.y, v.z, v.w};
#pragma unroll
    for (int j = 0; j < 4; ++j) split_bf16(vs[j], h[j], l[j]);
    __nv_bfloat162* ph = (__nv_bfloat162*)g_xh;
    __nv_bfloat162* pl = (__nv_bfloat162*)g_xl;
    ph[2 * i + 0] = __nv_bfloat162{h[0], h[1]};
    ph[2 * i + 1] = __nv_bfloat162{h[2], h[3]};
    pl[2 * i + 0] = __nv_bfloat162{l[0], l[1]};
    pl[2 * i + 1] = __nv_bfloat162{l[2], l[3]};
}

__global__ void split_w_kernel(const float* __restrict__ W) {
    int i = blockIdx.x * blockDim.x + threadIdx.x;
    if (i >= D_ * D_) return;
    int k = i / D_, e = i % D_;
    __nv_bfloat16 h, l;
    split_bf16(W[i], h, l);
    g_wth[e * D_ + k] = h;
    g_wtl[e * D_ + k] = l;
}

// ---------------------------------------------------------------------------
// MMA / ldmatrix / cp.async primitives
// ---------------------------------------------------------------------------
__device__ __forceinline__ void cpasync16(uint32_t dst, const void* src, bool valid) {
    int sz = valid ? 16 : 0;
    asm volatile("cp.async.cg.shared.global [%0], [%1], 16, %2;\n"
                 :: "r"(dst), "l"(src), "r"(sz));
}
__device__ __forceinline__ void cp_commit() { asm volatile("cp.async.commit_group;\n"); }
template <int N>
__device__ __forceinline__ void cp_wait() { asm volatile("cp.async.wait_group %0;\n" :: "n"(N)); }

__device__ __forceinline__ void ldsm4(uint32_t& r0, uint32_t& r1, uint32_t& r2, uint32_t& r3, uint32_t addr) {
    asm volatile("ldmatrix.sync.aligned.m8n8.x4.shared.b16 {%0,%1,%2,%3}, [%4];\n"
                 : "=r"(r0), "=r"(r1), "=r"(r2), "=r"(r3) : "r"(addr));
}
__device__ __forceinline__ void mma16816(float* c, const uint32_t* a, const uint32_t* b) {
    asm volatile("mma.sync.aligned.m16n8k16.row.col.f32.bf16.bf16.f32 "
                 "{%0,%1,%2,%3}, {%4,%5,%6,%7}, {%8,%9}, {%0,%1,%2,%3};\n"
                 : "+f"(c[0]), "+f"(c[1]), "+f"(c[2]), "+f"(c[3])
                 : "r"(a[0]), "r"(a[1]), "r"(a[2]), "r"(a[3]), "r"(b[0]), "r"(b[1]));
}

__device__ __forceinline__ float fast_sigmoid(float v) {
    return __fdividef(1.0f, 1.0f + __expf(-v));
}

// ---------------------------------------------------------------------------
// GEMM tile geometry — 3-stage ring, swizzled 64B rows (no padding)
//   swizzle: 16B granule seg' = seg ^ ((row>>1)&3)
//   8 ldmatrix rows -> phases {0,64,16,80,32,96,48,112} mod 128: conflict-free
// ---------------------------------------------------------------------------
#define BM 128
#define BN 128
#define BK 32
#define ROWB 64                                  // bytes per row (32 bf16)
#define ARR_BYTES (128 * ROWB)                   // 8192
#define STAGE_BYTES (4 * ARR_BYTES)              // 32768
#define NSTAGE 3
#define OFF_AH 0
#define OFF_AL (1 * ARR_BYTES)
#define OFF_BH (2 * ARR_BYTES)
#define OFF_BL (3 * ARR_BYTES)
#define SMEM_TOTAL (NSTAGE * STAGE_BYTES)        // 98304 -> 2 CTAs = 192KB/SM

__device__ __forceinline__ uint32_t swz(int row, int seg) {
    return (uint32_t)(row * ROWB + ((seg ^ ((row >> 1) & 3)) << 4));
}

// SIG=false: GEMM1  xW = x @ W      -> split to g_xwh/l
// SIG=true : GEMM2  out = sigmoid(xW @ x^T + b), batched over blockIdx.z
template <bool SIG>
__global__ __launch_bounds__(256, 2)
void gemm_bf16x3(const float* __restrict__ bias, float* __restrict__ Out)
{
    extern __shared__ char smem[];
    const uint32_t sbase = (uint32_t)__cvta_generic_to_shared(smem);

    const int M = SIG ? L_ : M1;
    const int N = SIG ? L_ : D_;

    const __nv_bfloat16* Ah = SIG ? g_xwh : g_xh;
    const __nv_bfloat16* Al = SIG ? g_xwl : g_xl;
    const __nv_bfloat16* Bh = SIG ? g_xh  : g_wth;
    const __nv_bfloat16* Bl = SIG ? g_xl  : g_wtl;
    if (SIG) {
        size_t off = (size_t)blockIdx.z * L_ * D_;
        Ah += off; Al += off; Bh += off; Bl += off;
    }

    const int m0 = blockIdx.y * BM;
    const int n0 = blockIdx.x * BN;
    const int tid = threadIdx.x;
    const int lane = tid & 31;
    const int wid = tid >> 5;
    const int wm = (wid >> 2) * 64;   // 0 / 64
    const int wn = (wid & 3) * 32;    // 0..96
    const int gid = lane >> 2, tig = lane & 3;

    float acc[4][4][4];
#pragma unroll
    for (int i = 0; i < 4; ++i)
#pragma unroll
        for (int j = 0; j < 4; ++j)
#pragma unroll
            for (int f = 0; f < 4; ++f) acc[i][j][f] = 0.f;

    // ldmatrix row bases (within tile) and k-granule bits
    const int a_m = wm + ((lane >> 3) & 1) * 8 + (lane & 7);   // + mi*16
    const int a_s = (lane >> 4) & 1;                            // k granule low bit
    const int b_n = wn + ((lane >> 4) & 1) * 8 + (lane & 7);   // + p*16
    const int b_s = (lane >> 3) & 1;
    // swizzle bits depend only on (base>>1)&3 (mi*16, p*16 are 0 mod 4 after >>1)
    const int a_swb = (a_m >> 1) & 3;
    const int b_swb = (b_n >> 1) & 3;

    // Stage loader: 4 arrays x 128 rows x 32 bf16 (4 x 16B swizzled granules)
    auto load_stage = [&](int kt, int s) {
        const int k0 = kt * BK;
        const uint32_t sb = sbase + s * STAGE_BYTES;
#pragma unroll
        for (int h = 0; h < 2; ++h) {
            int c = tid + h * 256;            // 0..511
            int row = c >> 2, seg = c & 3;
            bool av = (m0 + row) < M;
            bool bv = (n0 + row) < N;
            size_t aoff = (size_t)(av ? m0 + row : 0) * D_ + k0 + seg * 8;
            size_t boff = (size_t)(bv ? n0 + row : 0) * D_ + k0 + seg * 8;
            uint32_t sm = swz(row, seg);
            cpasync16(sb + OFF_AH + sm, Ah + aoff, av);
            cpasync16(sb + OFF_AL + sm, Al + aoff, av);
            cpasync16(sb + OFF_BH + sm, Bh + boff, bv);
            cpasync16(sb + OFF_BL + sm, Bl + boff, bv);
        }
        cp_commit();
    };

    const int KT = D_ / BK;   // 10
    load_stage(0, 0);
    load_stage(1, 1);

    int cbuf = 0;              // buffer holding stage kt
    int lbuf = 2;              // buffer to load stage kt+2 into

    for (int kt = 0; kt < KT; ++kt) {
        if (kt + 1 < KT) cp_wait<1>();   // stage kt complete (kt+1 may be in flight)
        else             cp_wait<0>();
        __syncthreads();                 // single barrier per stage (3-stage ring)
        if (kt + 2 < KT) load_stage(kt + 2, lbuf);

        const uint32_t sb = sbase + cbuf * STAGE_BYTES;
#pragma unroll
        for (int ks = 0; ks < 2; ++ks) {
            const uint32_t sxa = (uint32_t)(((ks * 2 + a_s) ^ a_swb) << 4);
            const uint32_t sxb = (uint32_t)(((ks * 2 + b_s) ^ b_swb) << 4);

            uint32_t ah[4][4], al[4][4], bh[2][4], bl[2][4];
            // -- load ah + bh, then hh term (reuse distance 16 per acc) --
#pragma unroll
            for (int mi = 0; mi < 4; ++mi) {
                uint32_t adr = sb + OFF_AH + (uint32_t)((a_m + mi * 16) * ROWB) + sxa;
                ldsm4(ah[mi][0], ah[mi][1], ah[mi][2], ah[mi][3], adr);
            }
#pragma unroll
            for (int p = 0; p < 2; ++p) {
                uint32_t adr = sb + OFF_BH + (uint32_t)((b_n + p * 16) * ROWB) + sxb;
                ldsm4(bh[p][0], bh[p][1], bh[p][2], bh[p][3], adr);
            }
#pragma unroll
            for (int mi = 0; mi < 4; ++mi)
#pragma unroll
                for (int ni = 0; ni < 4; ++ni)
                    mma16816(acc[mi][ni], ah[mi], &bh[ni >> 1][(ni & 1) * 2]);

            // -- load bl, hl term --
#pragma unroll
            for (int p = 0; p < 2; ++p) {
                uint32_t adr = sb + OFF_BL + (uint32_t)((b_n + p * 16) * ROWB) + sxb;
                ldsm4(bl[p][0], bl[p][1], bl[p][2], bl[p][3], adr);
            }
#pragma unroll
            for (int mi = 0; mi < 4; ++mi)
#pragma unroll
                for (int ni = 0; ni < 4; ++ni)
                    mma16816(acc[mi][ni], ah[mi], &bl[ni >> 1][(ni & 1) * 2]);

            // -- load al, lh term --
#pragma unroll
            for (int mi = 0; mi < 4; ++mi) {
                uint32_t adr = sb + OFF_AL + (uint32_t)((a_m + mi * 16) * ROWB) + sxa;
                ldsm4(al[mi][0], al[mi][1], al[mi][2], al[mi][3], adr);
            }
#pragma unroll
            for (int mi = 0; mi < 4; ++mi)
#pragma unroll
                for (int ni = 0; ni < 4; ++ni)
                    mma16816(acc[mi][ni], al[mi], &bh[ni >> 1][(ni & 1) * 2]);
        }

        cbuf = (cbuf == 2) ? 0 : cbuf + 1;
        lbuf = (lbuf == 2) ? 0 : lbuf + 1;
    }

    // -------------------- epilogue --------------------
    if (SIG) {
        const float bv = bias[0];
        float* Cb = Out + (size_t)blockIdx.z * L_ * L_;
#pragma unroll
        for (int mi = 0; mi < 4; ++mi)
#pragma unroll
            for (int half = 0; half < 2; ++half) {
                int gm = m0 + wm + mi * 16 + gid + half * 8;
                if (gm >= M) continue;
#pragma unroll
                for (int ni = 0; ni < 4; ++ni) {
                    int gn = n0 + wn + ni * 8 + 2 * tig;
                    if (gn >= N) continue;
                    float2 r;
                    r.x = fast_sigmoid(acc[mi][ni][half * 2 + 0] + bv);
                    r.y = fast_sigmoid(acc[mi][ni][half * 2 + 1] + bv);
                    *(float2*)&Cb[(size_t)gm * L_ + gn] = r;
                }
            }
    } else {
#pragma unroll
        for (int mi = 0; mi < 4; ++mi)
#pragma unroll
            for (int half = 0; half < 2; ++half) {
                int gm = m0 + wm + mi * 16 + gid + half * 8;
                if (gm >= M) continue;
#pragma unroll
                for (int ni = 0; ni < 4; ++ni) {
                    int gn = n0 + wn + ni * 8 + 2 * tig;
                    if (gn >= N) continue;
                    float v0 = acc[mi][ni][half * 2 + 0];
                    float v1 = acc[mi][ni][half * 2 + 1];
                    __nv_bfloat16 h0, l0, h1, l1;
                    split_bf16(v0, h0, l0);
                    split_bf16(v1, h1, l1);
                    size_t idx = (size_t)gm * D_ + gn;
                    *(__nv_bfloat162*)&g_xwh[idx] = __nv_bfloat162{h0, h1};
                    *(__nv_bfloat162*)&g_xwl[idx] = __nv_bfloat162{l0, l1};
                }
            }
    }
}

// ---------------------------------------------------------------------------
extern "C" void kernel_launch(void* const* d_in, const int* in_sizes, int n_in,
                              void* d_out, int out_size)
{
    const float* x  = (const float*)d_in[0];   // (B, L, D)
    const float* W  = (const float*)d_in[1];   // (D, D)
    const float* bb = (const float*)d_in[2];   // (1,)
    float* out = (float*)d_out;                // (B, L, L)

    (void)cudaFuncSetAttribute(gemm_bf16x3<false>, cudaFuncAttributeMaxDynamicSharedMemorySize, SMEM_TOTAL);
    (void)cudaFuncSetAttribute(gemm_bf16x3<true>,  cudaFuncAttributeMaxDynamicSharedMemorySize, SMEM_TOTAL);

    // 1) split inputs into bf16 hi/lo
    {
        int n4 = M1 * D_ / 4;
        split_x_kernel<<<(n4 + 255) / 256, 256>>>(x);
        split_w_kernel<<<(D_ * D_ + 255) / 256, 256>>>(W);
    }
    // 2) xW = x @ W  (writes split bf16 scratch)
    {
        dim3 grid((D_ + BN - 1) / BN, (M1 + BM - 1) / BM, 1);   // (3, 129)
        gemm_bf16x3<false><<<grid, 256, SMEM_TOTAL>>>(nullptr, nullptr);
    }
    // 3) out = sigmoid(xW @ x^T + b), batched
    {
        dim3 grid((L_ + BN - 1) / BN, (L_ + BM - 1) / BM, B_);  // (17, 17, 8)
        gemm_bf16x3<true><<<grid, 256, SMEM_TOTAL>>>(bb, out);
    }
}

// round 11
// speedup vs baseline: 3.5044x; 1.0437x over previous
#include <cuda_runtime.h>
#include <cuda_bf16.h>
#include <math.h>
#include <stdint.h>

// Problem constants
#define B_  8
#define L_  2050
#define D_  320
#define M1  (B_ * L_)   // 16400

// ---------------------------------------------------------------------------
// Device-global scratch (allocation-free rule)
// ---------------------------------------------------------------------------
__device__ __nv_bfloat16 g_xh[(size_t)M1 * D_];
__device__ __nv_bfloat16 g_xl[(size_t)M1 * D_];
__device__ __nv_bfloat16 g_wth[D_ * D_];   // W transposed: [e][k]
__device__ __nv_bfloat16 g_wtl[D_ * D_];
__device__ __nv_bfloat16 g_xwh[(size_t)M1 * D_];
__device__ __nv_bfloat16 g_xwl[(size_t)M1 * D_];

// ---------------------------------------------------------------------------
// Split helpers
// ---------------------------------------------------------------------------
__device__ __forceinline__ void split_bf16(float v, __nv_bfloat16& h, __nv_bfloat16& l) {
    h = __float2bfloat16(v);
    l = __float2bfloat16(v - __bfloat162float(h));
}

// Combined split: float4-quads of x, plus W (transpose-split) on low threads.
__global__ void split_all_kernel(const float* __restrict__ x, const float* __restrict__ W) {
    int i = blockIdx.x * blockDim.x + threadIdx.x;
    const int n4 = M1 * D_ / 4;
    if (i < n4) {
        float4 v = ((const float4*)x)[i];
        __nv_bfloat16 h[4], l[4];
        float vs[4] = {v.x, v.y, v.z, v.w};
#pragma unroll
        for (int j = 0; j < 4; ++j) split_bf16(vs[j], h[j], l[j]);
        __nv_bfloat162* ph = (__nv_bfloat162*)g_xh;
        __nv_bfloat162* pl = (__nv_bfloat162*)g_xl;
        ph[2 * i + 0] = __nv_bfloat162{h[0], h[1]};
        ph[2 * i + 1] = __nv_bfloat162{h[2], h[3]};
        pl[2 * i + 0] = __nv_bfloat162{l[0], l[1]};
        pl[2 * i + 1] = __nv_bfloat162{l[2], l[3]};
    }
    if (i < D_ * D_) {
        int k = i / D_, e = i % D_;
        __nv_bfloat16 h, l;
        split_bf16(W[i], h, l);
        g_wth[e * D_ + k] = h;
        g_wtl[e * D_ + k] = l;
    }
}

// ---------------------------------------------------------------------------
// MMA / ldmatrix / cp.async primitives
// ---------------------------------------------------------------------------
__device__ __forceinline__ void cpasync16(uint32_t dst, const void* src, bool valid) {
    int sz = valid ? 16 : 0;
    asm volatile("cp.async.cg.shared.global [%0], [%1], 16, %2;\n"
                 :: "r"(dst), "l"(src), "r"(sz));
}
__device__ __forceinline__ void cp_commit() { asm volatile("cp.async.commit_group;\n"); }
template <int N>
__device__ __forceinline__ void cp_wait() { asm volatile("cp.async.wait_group %0;\n" :: "n"(N)); }

__device__ __forceinline__ void ldsm4(uint32_t& r0, uint32_t& r1, uint32_t& r2, uint32_t& r3, uint32_t addr) {
    asm volatile("ldmatrix.sync.aligned.m8n8.x4.shared.b16 {%0,%1,%2,%3}, [%4];\n"
                 : "=r"(r0), "=r"(r1), "=r"(r2), "=r"(r3) : "r"(addr));
}
__device__ __forceinline__ void mma16816(float* c, const uint32_t* a, const uint32_t* b) {
    asm volatile("mma.sync.aligned.m16n8k16.row.col.f32.bf16.bf16.f32 "
                 "{%0,%1,%2,%3}, {%4,%5,%6,%7}, {%8,%9}, {%0,%1,%2,%3};\n"
                 : "+f"(c[0]), "+f"(c[1]), "+f"(c[2]), "+f"(c[3])
                 : "r"(a[0]), "r"(a[1]), "r"(a[2]), "r"(a[3]), "r"(b[0]), "r"(b[1]));
}

__device__ __forceinline__ float fast_sigmoid(float v) {
    return __fdividef(1.0f, 1.0f + __expf(-v));
}

// ---------------------------------------------------------------------------
// GEMM — 3-stage ring, swizzled 64B rows (no padding)
//   swizzle: 16B granule seg' = seg ^ ((row>>1)&3): conflict-free ldmatrix
// BM fixed 128; BN templated: 128 for GEMM2, 64 for GEMM1 (320 = 5x64, no waste)
// ---------------------------------------------------------------------------
#define BM 128
#define BK 32
#define ROWB 64                                  // bytes per row (32 bf16)
#define A_BYTES (128 * ROWB)                     // 8192
#define NSTAGE 3

__device__ __forceinline__ uint32_t swz(int row, int seg) {
    return (uint32_t)(row * ROWB + ((seg ^ ((row >> 1) & 3)) << 4));
}

template <int BNT> struct Geom {
    static constexpr int B_BYTES = BNT * ROWB;
    static constexpr int STAGE_BYTES = 2 * A_BYTES + 2 * B_BYTES;
    static constexpr int OFF_AH = 0;
    static constexpr int OFF_AL = A_BYTES;
    static constexpr int OFF_BH = 2 * A_BYTES;
    static constexpr int OFF_BL = 2 * A_BYTES + B_BYTES;
    static constexpr int SMEM = NSTAGE * STAGE_BYTES;   // 128: 96KB, 64: 72KB
    static constexpr int NI = BNT / 32;                 // n8-blocks per warp
    static constexpr int P  = BNT / 64;                 // b-ldsm4 per ks
};

// SIG=false: GEMM1  xW = x @ W      -> split to g_xwh/l   (BNT=64)
// SIG=true : GEMM2  out = sigmoid(xW @ x^T + b), batched  (BNT=128)
template <bool SIG, int BNT>
__global__ __launch_bounds__(256, 2)
void gemm_bf16x3(const float* __restrict__ bias, float* __restrict__ Out)
{
    using G = Geom<BNT>;
    extern __shared__ char smem[];
    const uint32_t sbase = (uint32_t)__cvta_generic_to_shared(smem);

    const int M = SIG ? L_ : M1;
    const int N = SIG ? L_ : D_;

    const __nv_bfloat16* Ah = SIG ? g_xwh : g_xh;
    const __nv_bfloat16* Al = SIG ? g_xwl : g_xl;
    const __nv_bfloat16* Bh = SIG ? g_xh  : g_wth;
    const __nv_bfloat16* Bl = SIG ? g_xl  : g_wtl;
    if (SIG) {
        size_t off = (size_t)blockIdx.z * L_ * D_;
        Ah += off; Al += off; Bh += off; Bl += off;
    }

    const int m0 = blockIdx.y * BM;
    const int n0 = blockIdx.x * BNT;
    const int tid = threadIdx.x;
    const int lane = tid & 31;
    const int wid = tid >> 5;
    const int wm = (wid >> 2) * 64;          // 0 / 64
    const int wn = (wid & 3) * (BNT / 4);    // stride 32 (BNT=128) or 16 (BNT=64)
    const int gid = lane >> 2, tig = lane & 3;

    float acc[4][G::NI][4];
#pragma unroll
    for (int i = 0; i < 4; ++i)
#pragma unroll
        for (int j = 0; j < G::NI; ++j)
#pragma unroll
            for (int f = 0; f < 4; ++f) acc[i][j][f] = 0.f;

    // ldmatrix row bases (within tile) and k-granule bits
    const int a_m = wm + ((lane >> 3) & 1) * 8 + (lane & 7);   // + mi*16
    const int a_s = (lane >> 4) & 1;
    const int b_n = wn + ((lane >> 4) & 1) * 8 + (lane & 7);   // + p*16
    const int b_s = (lane >> 3) & 1;
    const int a_swb = (a_m >> 1) & 3;
    const int b_swb = (b_n >> 1) & 3;

    // Stage loader: A 128 rows + B BNT rows, hi+lo, 4x16B swizzled granules/row
    auto load_stage = [&](int kt, int s) {
        const int k0 = kt * BK;
        const uint32_t sb = sbase + s * G::STAGE_BYTES;
#pragma unroll
        for (int h = 0; h < 2; ++h) {            // A: 512 slots
            int c = tid + h * 256;
            int row = c >> 2, seg = c & 3;
            bool av = (m0 + row) < M;
            size_t aoff = (size_t)(av ? m0 + row : 0) * D_ + k0 + seg * 8;
            uint32_t sm = swz(row, seg);
            cpasync16(sb + G::OFF_AH + sm, Ah + aoff, av);
            cpasync16(sb + G::OFF_AL + sm, Al + aoff, av);
        }
#pragma unroll
        for (int h = 0; h < BNT / 64; ++h) {     // B: BNT*4 slots
            int c = tid + h * 256;
            int row = c >> 2, seg = c & 3;
            bool bv = (n0 + row) < N;
            size_t boff = (size_t)(bv ? n0 + row : 0) * D_ + k0 + seg * 8;
            uint32_t sm = swz(row, seg);
            cpasync16(sb + G::OFF_BH + sm, Bh + boff, bv);
            cpasync16(sb + G::OFF_BL + sm, Bl + boff, bv);
        }
        cp_commit();
    };

    const int KT = D_ / BK;   // 10
    load_stage(0, 0);
    load_stage(1, 1);

    int cbuf = 0;              // buffer holding stage kt
    int lbuf = 2;              // buffer to load stage kt+2 into

    for (int kt = 0; kt < KT; ++kt) {
        if (kt + 1 < KT) cp_wait<1>();   // stage kt complete (kt+1 may be in flight)
        else             cp_wait<0>();
        __syncthreads();                 // single barrier per stage (3-stage ring)

        const uint32_t sb = sbase + cbuf * G::STAGE_BYTES;
#pragma unroll
        for (int ks = 0; ks < 2; ++ks) {
            const uint32_t sxa = (uint32_t)(((ks * 2 + a_s) ^ a_swb) << 4);
            const uint32_t sxb = (uint32_t)(((ks * 2 + b_s) ^ b_swb) << 4);

            uint32_t ah[4][4], al[4][4], bh[G::P][4], bl[G::P][4];
            // -- load ah + bh, then hh term (reuse distance NI*4 per acc) --
#pragma unroll
            for (int mi = 0; mi < 4; ++mi) {
                uint32_t adr = sb + G::OFF_AH + (uint32_t)((a_m + mi * 16) * ROWB) + sxa;
                ldsm4(ah[mi][0], ah[mi][1], ah[mi][2], ah[mi][3], adr);
            }
#pragma unroll
            for (int p = 0; p < G::P; ++p) {
                uint32_t adr = sb + G::OFF_BH + (uint32_t)((b_n + p * 16) * ROWB) + sxb;
                ldsm4(bh[p][0], bh[p][1], bh[p][2], bh[p][3], adr);
            }
#pragma unroll
            for (int mi = 0; mi < 4; ++mi)
#pragma unroll
                for (int ni = 0; ni < G::NI; ++ni)
                    mma16816(acc[mi][ni], ah[mi], &bh[ni >> 1][(ni & 1) * 2]);

            // issue next-stage prefetch here: its cp.async burst rides under MMAs
            if (ks == 0 && kt + 2 < KT) load_stage(kt + 2, lbuf);

            // -- load bl, hl term --
#pragma unroll
            for (int p = 0; p < G::P; ++p) {
                uint32_t adr = sb + G::OFF_BL + (uint32_t)((b_n + p * 16) * ROWB) + sxb;
                ldsm4(bl[p][0], bl[p][1], bl[p][2], bl[p][3], adr);
            }
#pragma unroll
            for (int mi = 0; mi < 4; ++mi)
#pragma unroll
                for (int ni = 0; ni < G::NI; ++ni)
                    mma16816(acc[mi][ni], ah[mi], &bl[ni >> 1][(ni & 1) * 2]);

            // -- load al, lh term --
#pragma unroll
            for (int mi = 0; mi < 4; ++mi) {
                uint32_t adr = sb + G::OFF_AL + (uint32_t)((a_m + mi * 16) * ROWB) + sxa;
                ldsm4(al[mi][0], al[mi][1], al[mi][2], al[mi][3], adr);
            }
#pragma unroll
            for (int mi = 0; mi < 4; ++mi)
#pragma unroll
                for (int ni = 0; ni < G::NI; ++ni)
                    mma16816(acc[mi][ni], al[mi], &bh[ni >> 1][(ni & 1) * 2]);
        }

        cbuf = (cbuf == 2) ? 0 : cbuf + 1;
        lbuf = (lbuf == 2) ? 0 : lbuf + 1;
    }

    // -------------------- epilogue --------------------
    if (SIG) {
        const float bv = bias[0];
        float* Cb = Out + (size_t)blockIdx.z * L_ * L_;
#pragma unroll
        for (int mi = 0; mi < 4; ++mi)
#pragma unroll
            for (int half = 0; half < 2; ++half) {
                int gm = m0 + wm + mi * 16 + gid + half * 8;
                if (gm >= M) continue;
#pragma unroll
                for (int ni = 0; ni < G::NI; ++ni) {
                    int gn = n0 + wn + ni * 8 + 2 * tig;
                    if (gn >= N) continue;
                    float2 r;
                    r.x = fast_sigmoid(acc[mi][ni][half * 2 + 0] + bv);
                    r.y = fast_sigmoid(acc[mi][ni][half * 2 + 1] + bv);
                    *(float2*)&Cb[(size_t)gm * L_ + gn] = r;
                }
            }
    } else {
#pragma unroll
        for (int mi = 0; mi < 4; ++mi)
#pragma unroll
            for (int half = 0; half < 2; ++half) {
                int gm = m0 + wm + mi * 16 + gid + half * 8;
                if (gm >= M) continue;
#pragma unroll
                for (int ni = 0; ni < G::NI; ++ni) {
                    int gn = n0 + wn + ni * 8 + 2 * tig;
                    if (gn >= N) continue;
                    float v0 = acc[mi][ni][half * 2 + 0];
                    float v1 = acc[mi][ni][half * 2 + 1];
                    __nv_bfloat16 h0, l0, h1, l1;
                    split_bf16(v0, h0, l0);
                    split_bf16(v1, h1, l1);
                    size_t idx = (size_t)gm * D_ + gn;
                    *(__nv_bfloat162*)&g_xwh[idx] = __nv_bfloat162{h0, h1};
                    *(__nv_bfloat162*)&g_xwl[idx] = __nv_bfloat162{l0, l1};
                }
            }
    }
}

// ---------------------------------------------------------------------------
extern "C" void kernel_launch(void* const* d_in, const int* in_sizes, int n_in,
                              void* d_out, int out_size)
{
    const float* x  = (const float*)d_in[0];   // (B, L, D)
    const float* W  = (const float*)d_in[1];   // (D, D)
    const float* bb = (const float*)d_in[2];   // (1,)
    float* out = (float*)d_out;                // (B, L, L)

    (void)cudaFuncSetAttribute(gemm_bf16x3<false, 64>,
                               cudaFuncAttributeMaxDynamicSharedMemorySize, Geom<64>::SMEM);
    (void)cudaFuncSetAttribute(gemm_bf16x3<true, 128>,
                               cudaFuncAttributeMaxDynamicSharedMemorySize, Geom<128>::SMEM);

    // 1) split x and W into bf16 hi/lo (single launch)
    {
        int n4 = M1 * D_ / 4;   // covers D_*D_ too
        split_all_kernel<<<(n4 + 255) / 256, 256>>>(x, W);
    }
    // 2) xW = x @ W  (BN=64: 320 = 5x64, zero padding waste)
    {
        dim3 grid(D_ / 64, (M1 + BM - 1) / BM, 1);              // (5, 129)
        gemm_bf16x3<false, 64><<<grid, 256, Geom<64>::SMEM>>>(nullptr, nullptr);
    }
    // 3) out = sigmoid(xW @ x^T + b), batched
    {
        dim3 grid((L_ + 127) / 128, (L_ + BM - 1) / BM, B_);    // (17, 17, 8)
        gemm_bf16x3<true, 128><<<grid, 256, Geom<128>::SMEM>>>(bb, out);
    }
}